// round 2
// baseline (speedup 1.0000x reference)
#include <cuda_runtime.h>
#include <cstddef>

// Problem constants
#define N_ROWS   16384      // 32*512
#define D_DIM    512
#define K_CENT   2048
#define EMA      0.99f
#define GAMMAF   1.0f
#define EPSF     1e-8f
#define ROWS_PER_BLK 8
#define NBLK_SM  (N_ROWS / ROWS_PER_BLK)   // 2048

// Output layout (float32, concatenated in reference return order)
#define OFF_Q    ((size_t)0)                          // 32*512*512   = 8388608
#define OFF_LOSS ((size_t)8388608)                    // 32*512*2048  = 33554432
#define OFF_IDX  ((size_t)41943040)                   // 1*32*512     = 16384
#define OFF_CB   ((size_t)41959424)                   // 1*2048*512   = 1048576
#define OFF_CNT  ((size_t)43008000)                   // 2048

// ---------------- scratch (static device memory; no allocations) -------------
__device__ float g_sim[(size_t)N_ROWS * K_CENT];          // 134 MB
__device__ int   g_nn[N_ROWS];
__device__ float g_div_part[(size_t)NBLK_SM * K_CENT];    // 16 MB
__device__ float g_div2[8 * K_CENT];
__device__ float g_h_part[NBLK_SM];
__device__ int   g_counts[K_CENT];
__device__ float g_loss;

// ---------------- kernel 0: reset count histogram ----------------------------
__global__ void vq_init() {
    int t = threadIdx.x;
    for (int k = t; k < K_CENT; k += 256) g_counts[k] = 0;
}

// ---------------- kernel 1: fp32 SGEMM  sim = A @ B^T ------------------------
// A: [N_ROWS, D] row-major, B: [K_CENT, D] row-major.
#define BM 128
#define BN 128
#define BK 16
#define TM 8
#define TN 8

__global__ __launch_bounds__(256, 2)
void vq_gemm(const float* __restrict__ A, const float* __restrict__ B) {
    __shared__ float As[2][BK][BM + 8];
    __shared__ float Bs[2][BK][BN + 8];

    const int tid = threadIdx.x;
    const int m0  = blockIdx.y * BM;
    const int n0  = blockIdx.x * BN;
    const int tx  = tid & 15;
    const int ty  = tid >> 4;

    float acc[TM][TN];
#pragma unroll
    for (int i = 0; i < TM; i++)
#pragma unroll
        for (int j = 0; j < TN; j++) acc[i][j] = 0.f;

    const int lrow0 = tid >> 2;            // 0..63
    const int lrow1 = (tid + 256) >> 2;    // 64..127
    const int lc    = (tid & 3) * 4;       // 0,4,8,12

    const float* Ab = A + (size_t)m0 * D_DIM;
    const float* Bb = B + (size_t)n0 * D_DIM;

    float4 ra0, ra1, rb0, rb1;

    // prologue: stage 0
    ra0 = *(const float4*)(Ab + (size_t)lrow0 * D_DIM + lc);
    ra1 = *(const float4*)(Ab + (size_t)lrow1 * D_DIM + lc);
    rb0 = *(const float4*)(Bb + (size_t)lrow0 * D_DIM + lc);
    rb1 = *(const float4*)(Bb + (size_t)lrow1 * D_DIM + lc);
    As[0][lc+0][lrow0]=ra0.x; As[0][lc+1][lrow0]=ra0.y; As[0][lc+2][lrow0]=ra0.z; As[0][lc+3][lrow0]=ra0.w;
    As[0][lc+0][lrow1]=ra1.x; As[0][lc+1][lrow1]=ra1.y; As[0][lc+2][lrow1]=ra1.z; As[0][lc+3][lrow1]=ra1.w;
    Bs[0][lc+0][lrow0]=rb0.x; Bs[0][lc+1][lrow0]=rb0.y; Bs[0][lc+2][lrow0]=rb0.z; Bs[0][lc+3][lrow0]=rb0.w;
    Bs[0][lc+0][lrow1]=rb1.x; Bs[0][lc+1][lrow1]=rb1.y; Bs[0][lc+2][lrow1]=rb1.z; Bs[0][lc+3][lrow1]=rb1.w;
    __syncthreads();

    const int NSTAGE = D_DIM / BK;   // 32
#pragma unroll 1
    for (int s = 0; s < NSTAGE; ++s) {
        const int cur = s & 1;
        if (s + 1 < NSTAGE) {
            const int ko = (s + 1) * BK;
            ra0 = *(const float4*)(Ab + (size_t)lrow0 * D_DIM + ko + lc);
            ra1 = *(const float4*)(Ab + (size_t)lrow1 * D_DIM + ko + lc);
            rb0 = *(const float4*)(Bb + (size_t)lrow0 * D_DIM + ko + lc);
            rb1 = *(const float4*)(Bb + (size_t)lrow1 * D_DIM + ko + lc);
        }
#pragma unroll
        for (int kk = 0; kk < BK; ++kk) {
            float a[TM], b[TN];
#pragma unroll
            for (int i = 0; i < TM; i++) a[i] = As[cur][kk][ty * TM + i];
#pragma unroll
            for (int j = 0; j < TN; j++) b[j] = Bs[cur][kk][tx * TN + j];
#pragma unroll
            for (int i = 0; i < TM; i++)
#pragma unroll
                for (int j = 0; j < TN; j++) acc[i][j] = fmaf(a[i], b[j], acc[i][j]);
        }
        if (s + 1 < NSTAGE) {
            const int nxt = cur ^ 1;
            As[nxt][lc+0][lrow0]=ra0.x; As[nxt][lc+1][lrow0]=ra0.y; As[nxt][lc+2][lrow0]=ra0.z; As[nxt][lc+3][lrow0]=ra0.w;
            As[nxt][lc+0][lrow1]=ra1.x; As[nxt][lc+1][lrow1]=ra1.y; As[nxt][lc+2][lrow1]=ra1.z; As[nxt][lc+3][lrow1]=ra1.w;
            Bs[nxt][lc+0][lrow0]=rb0.x; Bs[nxt][lc+1][lrow0]=rb0.y; Bs[nxt][lc+2][lrow0]=rb0.z; Bs[nxt][lc+3][lrow0]=rb0.w;
            Bs[nxt][lc+0][lrow1]=rb1.x; Bs[nxt][lc+1][lrow1]=rb1.y; Bs[nxt][lc+2][lrow1]=rb1.z; Bs[nxt][lc+3][lrow1]=rb1.w;
            __syncthreads();
        }
    }

    // epilogue
#pragma unroll
    for (int i = 0; i < TM; i++) {
        const size_t row = (size_t)(m0 + ty * TM + i);
        float* Cr = g_sim + row * K_CENT + n0 + tx * TN;
        float4 v0 = make_float4(acc[i][0], acc[i][1], acc[i][2], acc[i][3]);
        float4 v1 = make_float4(acc[i][4], acc[i][5], acc[i][6], acc[i][7]);
        *(float4*)(Cr)     = v0;
        *(float4*)(Cr + 4) = v1;
    }
}

// ---------------- kernel 2: softmax / argmax / entropy / diversity -----------
__global__ __launch_bounds__(256)
void vq_softmax(float* __restrict__ out_idx) {
    __shared__ float sdiv[K_CENT];     // per-block diversity partial (8 KB)
    __shared__ float redf[256];
    __shared__ int   redi[256];
    const int t = threadIdx.x;
    const int row0 = blockIdx.x * ROWS_PER_BLK;

#pragma unroll
    for (int j = 0; j < K_CENT / 256; j++) sdiv[t + j * 256] = 0.f;
    __syncthreads();

    float hacc = 0.f;  // sum over rows of sum_k p*log2(p+eps)

    for (int r = 0; r < ROWS_PER_BLK; ++r) {
        const int n = row0 + r;
        const float* simr = g_sim + (size_t)n * K_CENT;

        float v[8];
#pragma unroll
        for (int j = 0; j < 8; j++) v[j] = simr[t + j * 256];

        // local max with first-occurrence tie-break (ascending index scan)
        float mv = v[0]; int mi = t;
#pragma unroll
        for (int j = 1; j < 8; j++) {
            int c = t + j * 256;
            if (v[j] > mv) { mv = v[j]; mi = c; }
        }
        redf[t] = mv; redi[t] = mi;
        __syncthreads();
        for (int s = 128; s > 0; s >>= 1) {
            if (t < s) {
                float ov = redf[t + s]; int oi = redi[t + s];
                if (ov > redf[t] || (ov == redf[t] && oi < redi[t])) { redf[t] = ov; redi[t] = oi; }
            }
            __syncthreads();
        }
        const float rowmax = redf[0];
        const int   rowidx = redi[0];

        float e[8]; float lsum = 0.f;
#pragma unroll
        for (int j = 0; j < 8; j++) { e[j] = expf(v[j] - rowmax); lsum += e[j]; }
        __syncthreads();                  // everyone done reading redf[0]
        redf[t] = lsum;
        __syncthreads();
        for (int s = 128; s > 0; s >>= 1) { if (t < s) redf[t] += redf[t + s]; __syncthreads(); }
        const float inv = 1.0f / redf[0];

#pragma unroll
        for (int j = 0; j < 8; j++) {
            float p = e[j] * inv;
            sdiv[t + j * 256] += p;           // exclusive per-thread columns: no race
            hacc += p * log2f(p + EPSF);
        }
        if (t == 0) {
            g_nn[n] = rowidx;
            out_idx[n] = (float)rowidx;
            atomicAdd(&g_counts[rowidx], 1);  // exact integer adds: deterministic
        }
        __syncthreads();                      // before redf reuse next row
    }

#pragma unroll
    for (int j = 0; j < K_CENT / 256; j++)
        g_div_part[(size_t)blockIdx.x * K_CENT + t + j * 256] = sdiv[t + j * 256];

    redf[t] = hacc;
    __syncthreads();
    for (int s = 128; s > 0; s >>= 1) { if (t < s) redf[t] += redf[t + s]; __syncthreads(); }
    if (t == 0) g_h_part[blockIdx.x] = redf[0];
}

// ---------------- kernel 3: deterministic diversity reduction (stage 1) ------
__global__ __launch_bounds__(256)
void vq_div_reduce() {
    const int k = blockIdx.x * 256 + threadIdx.x;  // 0..2047 (gridDim.x = 8)
    const int chunk = blockIdx.y;                  // 0..7
    const int b0 = chunk * 256;
    float s0 = 0.f, s1 = 0.f, s2 = 0.f, s3 = 0.f;
    for (int b = 0; b < 256; b += 4) {
        s0 += g_div_part[(size_t)(b0 + b + 0) * K_CENT + k];
        s1 += g_div_part[(size_t)(b0 + b + 1) * K_CENT + k];
        s2 += g_div_part[(size_t)(b0 + b + 2) * K_CENT + k];
        s3 += g_div_part[(size_t)(b0 + b + 3) * K_CENT + k];
    }
    g_div2[chunk * K_CENT + k] = (s0 + s1) + (s2 + s3);
}

// ---------------- kernel 4: finalize loss + EMA counts -----------------------
__global__ __launch_bounds__(256)
void vq_finalize(const float* __restrict__ cluster_counts,
                 const int* __restrict__ train,
                 float* __restrict__ out_counts) {
    __shared__ float redf[256];
    const int t = threadIdx.x;
    const int tr = train[0];

    float hdiv = 0.f;   // sum_k d*log2(d+eps)
    for (int k = t; k < K_CENT; k += 256) {
        float s = 0.f;
#pragma unroll
        for (int ch = 0; ch < 8; ch++) s += g_div2[ch * K_CENT + k];
        float d = s * (1.0f / (float)N_ROWS);
        hdiv += d * log2f(d + EPSF);
        float cnt = (float)g_counts[k];
        float oc  = cluster_counts[k];
        out_counts[k] = tr ? (EMA * oc + (1.0f - EMA) * cnt) : oc;
    }
    float hsum = 0.f;
    for (int i = t; i < NBLK_SM; i += 256) hsum += g_h_part[i];

    redf[t] = hdiv;
    __syncthreads();
    for (int s = 128; s > 0; s >>= 1) { if (t < s) redf[t] += redf[t + s]; __syncthreads(); }
    const float hdiv_tot = redf[0];
    __syncthreads();
    redf[t] = hsum;
    __syncthreads();
    for (int s = 128; s > 0; s >>= 1) { if (t < s) redf[t] += redf[t + s]; __syncthreads(); }
    if (t == 0) {
        float h_clust     = -(redf[0] / (float)N_ROWS);
        float h_diversity = -hdiv_tot;
        g_loss = h_clust - GAMMAF * h_diversity;
    }
}

// ---------------- kernel 5: broadcast-fill quantization_loss -----------------
__global__ __launch_bounds__(256)
void vq_fill(float* __restrict__ dst) {
    const float v = g_loss;
    const float4 f = make_float4(v, v, v, v);
    size_t i = (size_t)blockIdx.x * 256 + threadIdx.x;   // grid 8192 -> 2097152 threads
#pragma unroll
    for (int j = 0; j < 4; j++)
        ((float4*)dst)[i + (size_t)j * 2097152] = f;
}

// ---------------- kernel 6: gather + center + normalize + STE ----------------
__global__ __launch_bounds__(128)
void vq_quantize(const float* __restrict__ inputs,
                 const float* __restrict__ codebook,
                 float* __restrict__ out_q) {
    __shared__ float red[128];
    const int n = blockIdx.x;
    const int t = threadIdx.x;
    const int idx = g_nn[n];

    const float4 q = ((const float4*)(codebook + (size_t)idx * D_DIM))[t];
    red[t] = q.x + q.y + q.z + q.w;
    __syncthreads();
    for (int s = 64; s > 0; s >>= 1) { if (t < s) red[t] += red[t + s]; __syncthreads(); }
    const float mean = red[0] * (1.0f / (float)D_DIM);
    __syncthreads();

    const float cx = q.x - mean, cy = q.y - mean, cz = q.z - mean, cw = q.w - mean;
    red[t] = cx * cx + cy * cy + cz * cz + cw * cw;
    __syncthreads();
    for (int s = 64; s > 0; s >>= 1) { if (t < s) red[t] += red[t + s]; __syncthreads(); }
    const float inv = 1.0f / sqrtf(red[0]);

    const float4 x = ((const float4*)(inputs + (size_t)n * D_DIM))[t];
    float4 o;
    o.x = x.x + (cx * inv - x.x);
    o.y = x.y + (cy * inv - x.y);
    o.z = x.z + (cz * inv - x.z);
    o.w = x.w + (cw * inv - x.w);
    ((float4*)out_q)[(size_t)n * (D_DIM / 4) + t] = o;
}

// ---------------- launcher ---------------------------------------------------
extern "C" void kernel_launch(void* const* d_in, const int* in_sizes, int n_in,
                              void* d_out, int out_size) {
    const float* inputs   = (const float*)d_in[0];   // [32,512,512]
    const float* codebook = (const float*)d_in[1];   // [2048,512]
    const float* ccounts  = (const float*)d_in[2];   // [2048]
    const int*   train    = (const int*)d_in[3];     // scalar
    float* out = (float*)d_out;

    vq_init<<<1, 256>>>();
    vq_gemm<<<dim3(K_CENT / BN, N_ROWS / BM), 256>>>(inputs, codebook);
    vq_softmax<<<NBLK_SM, 256>>>(out + OFF_IDX);
    vq_div_reduce<<<dim3(8, 8), 256>>>();
    vq_finalize<<<1, 256>>>(ccounts, train, out + OFF_CNT);
    vq_fill<<<8192, 256>>>(out + OFF_LOSS);
    vq_quantize<<<N_ROWS, 128>>>(inputs, codebook, out + OFF_Q);
    cudaMemcpyAsync(out + OFF_CB, d_in[1], (size_t)K_CENT * D_DIM * sizeof(float),
                    cudaMemcpyDeviceToDevice, 0);
    (void)in_sizes; (void)n_in; (void)out_size;
}

// round 4
// speedup vs baseline: 1.9846x; 1.9846x over previous
#include <cuda_runtime.h>
#include <cuda_bf16.h>
#include <cstdint>
#include <cstddef>

// Problem constants
#define N_ROWS   16384
#define D_DIM    512
#define K_CENT   2048
#define EMA      0.99f
#define GAMMAF   1.0f
#define EPSF     1e-8f
#define DELTA    1e-3f
#define ROWS_PER_BLK 16
#define NBLK_SM  (N_ROWS / ROWS_PER_BLK)   // 1024

// Output layout (float32, concatenated in reference return order)
#define OFF_Q    ((size_t)0)
#define OFF_LOSS ((size_t)8388608)
#define OFF_IDX  ((size_t)41943040)
#define OFF_CB   ((size_t)41959424)
#define OFF_CNT  ((size_t)43008000)

// ---------------- scratch (static device memory) -----------------------------
__device__ float g_sim[(size_t)N_ROWS * K_CENT];          // 134 MB
__device__ int   g_nn[N_ROWS];
__device__ float g_div_part[(size_t)NBLK_SM * K_CENT];    // 8 MB
__device__ float g_div2[4 * K_CENT];
__device__ float g_h_part[NBLK_SM];
__device__ int   g_counts[K_CENT];
__device__ float g_loss;
__device__ __align__(16) __nv_bfloat16 g_Abf[2][(size_t)N_ROWS * D_DIM];  // 32 MB
__device__ __align__(16) __nv_bfloat16 g_Bbf[2][(size_t)K_CENT * D_DIM];  // 4 MB

__device__ __forceinline__ uint32_t smem_u32(const void* p) {
    uint32_t a;
    asm("{ .reg .u64 t; cvta.to.shared.u64 t, %1; cvt.u32.u64 %0, t; }" : "=r"(a) : "l"(p));
    return a;
}

// ---------------- kernel: bf16x2 split ---------------------------------------
__global__ __launch_bounds__(256)
void vq_split(const float* __restrict__ A, const float* __restrict__ B) {
    const size_t NA4 = (size_t)N_ROWS * D_DIM / 4;   // 2097152
    const size_t NB4 = (size_t)K_CENT * D_DIM / 4;   // 262144
    size_t i = (size_t)blockIdx.x * 256 + threadIdx.x;
    if (i >= NA4 + NB4) return;
    const bool isA = (i < NA4);
    const float4 x = isA ? ((const float4*)A)[i] : ((const float4*)B)[i - NA4];
    float v[4] = {x.x, x.y, x.z, x.w};
    __nv_bfloat16 s0[4], s1[4];
#pragma unroll
    for (int j = 0; j < 4; j++) {
        s0[j] = __float2bfloat16_rn(v[j]);
        float r = v[j] - __bfloat162float(s0[j]);
        s1[j] = __float2bfloat16_rn(r);
    }
    size_t e = (isA ? i : (i - NA4)) * 4;
    __nv_bfloat16* d0 = isA ? g_Abf[0] : g_Bbf[0];
    __nv_bfloat16* d1 = isA ? g_Abf[1] : g_Bbf[1];
    ((__nv_bfloat162*)(d0 + e))[0] = __nv_bfloat162(s0[0], s0[1]);
    ((__nv_bfloat162*)(d0 + e))[1] = __nv_bfloat162(s0[2], s0[3]);
    ((__nv_bfloat162*)(d1 + e))[0] = __nv_bfloat162(s1[0], s1[1]);
    ((__nv_bfloat162*)(d1 + e))[1] = __nv_bfloat162(s1[2], s1[3]);
}

// ---------------- kernel: reset count histogram ------------------------------
__global__ void vq_init() {
    int t = threadIdx.x;
    for (int k = t; k < K_CENT; k += 256) g_counts[k] = 0;
}

// ---------------- kernel: mma.sync bf16x2 GEMM  sim = A @ B^T ----------------
// K_eff = 1536 = 3 segments of 512: (A0,B0), (A0,B1), (A1,B0)
#define GBM 128
#define GBN 128
#define GSTAGE_BYTES 20480        // A tile 10240 + B tile 10240 (128 rows x 40 halves)
#define GSM_TOTAL (3 * GSTAGE_BYTES)   // 61440
#define GLD 40                    // halves per smem row (80 bytes, conflict-free)

__device__ __forceinline__ void g_load_stage(uint32_t smemU, int st, int kstep,
                                             int m0, int n0, int tid) {
    const int seg = kstep >> 4;                 // 0..2
    const int kin = (kstep & 15) * 32;
    const __nv_bfloat16* __restrict__ gA = g_Abf[seg == 2 ? 1 : 0];
    const __nv_bfloat16* __restrict__ gB = g_Bbf[seg == 1 ? 1 : 0];
    const uint32_t sA = smemU + st * GSTAGE_BYTES;
    const uint32_t sB = sA + 10240;
#pragma unroll
    for (int h = 0; h < 2; h++) {
        const int c = tid + h * 256;            // 0..511
        const int row = c >> 2, q = c & 3;
        const void* srcA = gA + (size_t)(m0 + row) * D_DIM + kin + q * 8;
        const uint32_t dstA = sA + row * 80 + q * 16;
        asm volatile("cp.async.cg.shared.global [%0], [%1], 16;" :: "r"(dstA), "l"(srcA));
        const void* srcB = gB + (size_t)(n0 + row) * D_DIM + kin + q * 8;
        const uint32_t dstB = sB + row * 80 + q * 16;
        asm volatile("cp.async.cg.shared.global [%0], [%1], 16;" :: "r"(dstB), "l"(srcB));
    }
}

__global__ __launch_bounds__(256, 2)
void vq_gemm_mma() {
    extern __shared__ char gsm[];
    const uint32_t smemU = smem_u32(gsm);
    const int tid = threadIdx.x;
    const int lane = tid & 31;
    const int w = tid >> 5;
    const int wm = (w & 1) * 64;       // warp m-offset in tile
    const int wn = (w >> 1) * 32;      // warp n-offset in tile
    const int n0 = blockIdx.x * GBN;
    const int m0 = blockIdx.y * GBM;

    float acc[4][4][4];
#pragma unroll
    for (int a = 0; a < 4; a++)
#pragma unroll
        for (int b = 0; b < 4; b++)
#pragma unroll
            for (int c = 0; c < 4; c++) acc[a][b][c] = 0.f;

    g_load_stage(smemU, 0, 0, m0, n0, tid);
    asm volatile("cp.async.commit_group;" ::: "memory");
    g_load_stage(smemU, 1, 1, m0, n0, tid);
    asm volatile("cp.async.commit_group;" ::: "memory");

    int st = 0, ls = 2;
    for (int i = 0; i < 48; i++) {
        if (i + 2 < 48) asm volatile("cp.async.wait_group 1;" ::: "memory");
        else            asm volatile("cp.async.wait_group 0;" ::: "memory");
        __syncthreads();
        if (i + 2 < 48) {
            g_load_stage(smemU, ls, i + 2, m0, n0, tid);
            asm volatile("cp.async.commit_group;" ::: "memory");
            ls = (ls == 2) ? 0 : ls + 1;
        }
        const uint32_t sA = smemU + st * GSTAGE_BYTES;
        const uint32_t sB = sA + 10240;
#pragma unroll
        for (int k16 = 0; k16 < 32; k16 += 16) {
            uint32_t a[4][4], b[2][4];
#pragma unroll
            for (int mt = 0; mt < 4; mt++) {
                const uint32_t addr = sA + (wm + mt * 16 + (lane & 15)) * 80
                                         + (k16 + ((lane >> 4) << 3)) * 2;
                asm volatile("ldmatrix.sync.aligned.m8n8.x4.shared.b16 {%0,%1,%2,%3}, [%4];"
                    : "=r"(a[mt][0]), "=r"(a[mt][1]), "=r"(a[mt][2]), "=r"(a[mt][3])
                    : "r"(addr));
            }
#pragma unroll
            for (int nt2 = 0; nt2 < 2; nt2++) {
                const uint32_t addr = sB + (wn + nt2 * 16 + ((lane >> 4) & 1) * 8 + (lane & 7)) * 80
                                         + (k16 + ((lane >> 3) & 1) * 8) * 2;
                asm volatile("ldmatrix.sync.aligned.m8n8.x4.shared.b16 {%0,%1,%2,%3}, [%4];"
                    : "=r"(b[nt2][0]), "=r"(b[nt2][1]), "=r"(b[nt2][2]), "=r"(b[nt2][3])
                    : "r"(addr));
            }
#pragma unroll
            for (int mt = 0; mt < 4; mt++)
#pragma unroll
                for (int nt = 0; nt < 4; nt++) {
                    asm volatile(
                        "mma.sync.aligned.m16n8k16.row.col.f32.bf16.bf16.f32 "
                        "{%0,%1,%2,%3},{%4,%5,%6,%7},{%8,%9},{%0,%1,%2,%3};"
                        : "+f"(acc[mt][nt][0]), "+f"(acc[mt][nt][1]),
                          "+f"(acc[mt][nt][2]), "+f"(acc[mt][nt][3])
                        : "r"(a[mt][0]), "r"(a[mt][1]), "r"(a[mt][2]), "r"(a[mt][3]),
                          "r"(b[nt >> 1][(nt & 1) * 2]), "r"(b[nt >> 1][(nt & 1) * 2 + 1]));
                }
        }
        st = (st == 2) ? 0 : st + 1;
    }

    // epilogue: direct float2 stores
#pragma unroll
    for (int mt = 0; mt < 4; mt++) {
        const int r0 = m0 + wm + mt * 16 + (lane >> 2);
        const int cb = n0 + wn + (lane & 3) * 2;
#pragma unroll
        for (int nt = 0; nt < 4; nt++) {
            float* p0 = g_sim + (size_t)r0 * K_CENT + cb + nt * 8;
            float* p1 = p0 + (size_t)8 * K_CENT;
            *(float2*)p0 = make_float2(acc[mt][nt][0], acc[mt][nt][1]);
            *(float2*)p1 = make_float2(acc[mt][nt][2], acc[mt][nt][3]);
        }
    }
}

// ---------------- kernel: softmax / exact argmax / entropy / diversity -------
__global__ __launch_bounds__(256)
void vq_softmax(const float* __restrict__ inputs, const float* __restrict__ codebook,
                float* __restrict__ out_idx) {
    __shared__ float sdiv[K_CENT];
    __shared__ float warr[8], wS[8], wT[8];
    __shared__ int   cand[32];
    __shared__ int   ncand;
    const int t = threadIdx.x;
    const int lane = t & 31;
    const int w = t >> 5;
    const int row0 = blockIdx.x * ROWS_PER_BLK;

    for (int j = t; j < K_CENT; j += 256) sdiv[j] = 0.f;
    float hacc = 0.f;
    __syncthreads();

    for (int r = 0; r < ROWS_PER_BLK; ++r) {
        const int n = row0 + r;
        const float* simr = g_sim + (size_t)n * K_CENT;

        float v[8];
#pragma unroll
        for (int j = 0; j < 8; j++) v[j] = simr[t + j * 256];

        float mv = v[0];
#pragma unroll
        for (int j = 1; j < 8; j++) mv = fmaxf(mv, v[j]);
#pragma unroll
        for (int o = 16; o > 0; o >>= 1) mv = fmaxf(mv, __shfl_xor_sync(0xffffffffu, mv, o));
        if (lane == 0) warr[w] = mv;
        if (t == 0) ncand = 0;
        __syncthreads();
        float rowmax = warr[0];
#pragma unroll
        for (int k = 1; k < 8; k++) rowmax = fmaxf(rowmax, warr[k]);

        // candidates within DELTA of approx max (exact refinement below)
#pragma unroll
        for (int j = 0; j < 8; j++) {
            if (v[j] >= rowmax - DELTA) {
                int s = atomicAdd(&ncand, 1);
                if (s < 32) cand[s] = t + j * 256;
            }
        }

        float e[8], ls = 0.f, ts = 0.f;
#pragma unroll
        for (int j = 0; j < 8; j++) {
            float u = v[j] - rowmax;
            float ee = __expf(u);
            e[j] = ee; ls += ee; ts += ee * u;
        }
#pragma unroll
        for (int o = 16; o > 0; o >>= 1) {
            ls += __shfl_xor_sync(0xffffffffu, ls, o);
            ts += __shfl_xor_sync(0xffffffffu, ts, o);
        }
        if (lane == 0) { wS[w] = ls; wT[w] = ts; }
        __syncthreads();
        float S = 0.f, T = 0.f;
#pragma unroll
        for (int k = 0; k < 8; k++) { S += wS[k]; T += wT[k]; }
        const float invS = 1.0f / S;

#pragma unroll
        for (int j = 0; j < 8; j++) sdiv[t + j * 256] += e[j] * invS;
        // sum_k p*log2(p) = log2e*(T/S) - log2(S)   (eps inside log is negligible)
        if (t == 0) hacc += 1.44269504f * (T * invS) - __log2f(S);

        // exact fp32 refinement of argmax (warp 0)
        if (w == 0) {
            const int nc = min(ncand, 32);
            float bestv = -3.4e38f; int besti = 0x7fffffff;
            const float4* ar = (const float4*)(inputs + (size_t)n * D_DIM);
            for (int c = 0; c < nc; ++c) {
                const int k = cand[c];
                const float4* br = (const float4*)(codebook + (size_t)k * D_DIM);
                float part = 0.f;
#pragma unroll 4
                for (int i = lane; i < D_DIM / 4; i += 32) {
                    float4 a = ar[i], b = br[i];
                    part += a.x * b.x + a.y * b.y + a.z * b.z + a.w * b.w;
                }
#pragma unroll
                for (int o = 16; o > 0; o >>= 1)
                    part += __shfl_xor_sync(0xffffffffu, part, o);
                if (part > bestv || (part == bestv && k < besti)) { bestv = part; besti = k; }
            }
            if (lane == 0) {
                g_nn[n] = besti;
                out_idx[n] = (float)besti;
                atomicAdd(&g_counts[besti], 1);
            }
        }
        __syncthreads();
    }

    for (int j = t; j < K_CENT; j += 256)
        g_div_part[(size_t)blockIdx.x * K_CENT + j] = sdiv[j];
    if (t == 0) g_h_part[blockIdx.x] = hacc;
}

// ---------------- kernel: deterministic diversity reduction ------------------
__global__ __launch_bounds__(256)
void vq_div_reduce() {
    const int k = blockIdx.x * 256 + threadIdx.x;  // 0..2047 (gridDim.x = 8)
    const int chunk = blockIdx.y;                  // 0..3
    const int b0 = chunk * 256;
    float s0 = 0.f, s1 = 0.f, s2 = 0.f, s3 = 0.f;
    for (int b = 0; b < 256; b += 4) {
        s0 += g_div_part[(size_t)(b0 + b + 0) * K_CENT + k];
        s1 += g_div_part[(size_t)(b0 + b + 1) * K_CENT + k];
        s2 += g_div_part[(size_t)(b0 + b + 2) * K_CENT + k];
        s3 += g_div_part[(size_t)(b0 + b + 3) * K_CENT + k];
    }
    g_div2[chunk * K_CENT + k] = (s0 + s1) + (s2 + s3);
}

// ---------------- kernel: finalize loss + EMA counts -------------------------
__global__ __launch_bounds__(256)
void vq_finalize(const float* __restrict__ cluster_counts,
                 const int* __restrict__ train,
                 float* __restrict__ out_counts) {
    __shared__ float redf[256];
    const int t = threadIdx.x;
    const int tr = train[0];

    float hdiv = 0.f;
    for (int k = t; k < K_CENT; k += 256) {
        float s = 0.f;
#pragma unroll
        for (int ch = 0; ch < 4; ch++) s += g_div2[ch * K_CENT + k];
        float d = s * (1.0f / (float)N_ROWS);
        hdiv += d * __log2f(d + EPSF);
        float cnt = (float)g_counts[k];
        float oc  = cluster_counts[k];
        out_counts[k] = tr ? (EMA * oc + (1.0f - EMA) * cnt) : oc;
    }
    float hsum = 0.f;
    for (int i = t; i < NBLK_SM; i += 256) hsum += g_h_part[i];

    redf[t] = hdiv;
    __syncthreads();
    for (int s = 128; s > 0; s >>= 1) { if (t < s) redf[t] += redf[t + s]; __syncthreads(); }
    const float hdiv_tot = redf[0];
    __syncthreads();
    redf[t] = hsum;
    __syncthreads();
    for (int s = 128; s > 0; s >>= 1) { if (t < s) redf[t] += redf[t + s]; __syncthreads(); }
    if (t == 0) {
        float h_clust     = -(redf[0] / (float)N_ROWS);
        float h_diversity = -hdiv_tot;
        g_loss = h_clust - GAMMAF * h_diversity;
    }
}

// ---------------- kernel: broadcast-fill quantization_loss -------------------
__global__ __launch_bounds__(256)
void vq_fill(float* __restrict__ dst) {
    const float v = g_loss;
    const float4 f = make_float4(v, v, v, v);
    size_t i = (size_t)blockIdx.x * 256 + threadIdx.x;
#pragma unroll
    for (int j = 0; j < 4; j++)
        ((float4*)dst)[i + (size_t)j * 2097152] = f;
}

// ---------------- kernel: gather + center + normalize + STE ------------------
__global__ __launch_bounds__(128)
void vq_quantize(const float* __restrict__ inputs,
                 const float* __restrict__ codebook,
                 float* __restrict__ out_q) {
    __shared__ float red[128];
    const int n = blockIdx.x;
    const int t = threadIdx.x;
    const int idx = g_nn[n];

    const float4 q = ((const float4*)(codebook + (size_t)idx * D_DIM))[t];
    red[t] = q.x + q.y + q.z + q.w;
    __syncthreads();
    for (int s = 64; s > 0; s >>= 1) { if (t < s) red[t] += red[t + s]; __syncthreads(); }
    const float mean = red[0] * (1.0f / (float)D_DIM);
    __syncthreads();

    const float cx = q.x - mean, cy = q.y - mean, cz = q.z - mean, cw = q.w - mean;
    red[t] = cx * cx + cy * cy + cz * cz + cw * cw;
    __syncthreads();
    for (int s = 64; s > 0; s >>= 1) { if (t < s) red[t] += red[t + s]; __syncthreads(); }
    const float inv = 1.0f / sqrtf(red[0]);

    const float4 x = ((const float4*)(inputs + (size_t)n * D_DIM))[t];
    float4 o;
    o.x = x.x + (cx * inv - x.x);
    o.y = x.y + (cy * inv - x.y);
    o.z = x.z + (cz * inv - x.z);
    o.w = x.w + (cw * inv - x.w);
    ((float4*)out_q)[(size_t)n * (D_DIM / 4) + t] = o;
}

// ---------------- launcher ---------------------------------------------------
extern "C" void kernel_launch(void* const* d_in, const int* in_sizes, int n_in,
                              void* d_out, int out_size) {
    const float* inputs   = (const float*)d_in[0];
    const float* codebook = (const float*)d_in[1];
    const float* ccounts  = (const float*)d_in[2];
    const int*   train    = (const int*)d_in[3];
    float* out = (float*)d_out;

    static bool attr_set = false;
    if (!attr_set) {
        cudaFuncSetAttribute(vq_gemm_mma, cudaFuncAttributeMaxDynamicSharedMemorySize, GSM_TOTAL);
        attr_set = true;
    }

    vq_split<<<9216, 256>>>(inputs, codebook);
    vq_init<<<1, 256>>>();
    vq_gemm_mma<<<dim3(K_CENT / GBN, N_ROWS / GBM), 256, GSM_TOTAL>>>();
    vq_softmax<<<NBLK_SM, 256>>>(inputs, codebook, out + OFF_IDX);
    vq_div_reduce<<<dim3(8, 4), 256>>>();
    vq_finalize<<<1, 256>>>(ccounts, train, out + OFF_CNT);
    vq_fill<<<8192, 256>>>(out + OFF_LOSS);
    vq_quantize<<<N_ROWS, 128>>>(inputs, codebook, out + OFF_Q);
    cudaMemcpyAsync(out + OFF_CB, d_in[1], (size_t)K_CENT * D_DIM * sizeof(float),
                    cudaMemcpyDeviceToDevice, 0);
    (void)in_sizes; (void)n_in; (void)out_size;
}

// round 5
// speedup vs baseline: 3.6018x; 1.8149x over previous
#include <cuda_runtime.h>
#include <cuda_bf16.h>
#include <cstdint>
#include <cstddef>

// Problem constants
#define N_ROWS   16384
#define D_DIM    512
#define K_CENT   2048
#define EMA      0.99f
#define GAMMAF   1.0f
#define EPSF     1e-8f
#define DELTA    1.5e-2f
#define ROWS_PER_BLK 16
#define NBLK_SM  (N_ROWS / ROWS_PER_BLK)   // 1024

// Output layout (float32, concatenated in reference return order)
#define OFF_Q    ((size_t)0)
#define OFF_LOSS ((size_t)8388608)
#define OFF_IDX  ((size_t)41943040)
#define OFF_CB   ((size_t)41959424)
#define OFF_CNT  ((size_t)43008000)

// ---------------- scratch (static device memory) -----------------------------
__device__ __align__(16) __nv_bfloat16 g_simh[(size_t)N_ROWS * K_CENT];   // 67 MB
__device__ int   g_nn[N_ROWS];
__device__ float g_div_part[(size_t)NBLK_SM * K_CENT];    // 8 MB
__device__ float g_div2[16 * K_CENT];
__device__ float g_h_part[NBLK_SM];
__device__ int   g_counts[K_CENT];
__device__ float g_loss;
__device__ __align__(16) __nv_bfloat16 g_Abf[(size_t)N_ROWS * D_DIM];  // 16.8 MB
__device__ __align__(16) __nv_bfloat16 g_Bbf[(size_t)K_CENT * D_DIM];  // 2 MB

__device__ __forceinline__ uint32_t smem_u32(const void* p) {
    uint32_t a;
    asm("{ .reg .u64 t; cvta.to.shared.u64 t, %1; cvt.u32.u64 %0, t; }" : "=r"(a) : "l"(p));
    return a;
}

// ---------------- kernel: fp32 -> bf16 convert --------------------------------
__global__ __launch_bounds__(256)
void vq_convert(const float* __restrict__ A, const float* __restrict__ B) {
    const size_t NA4 = (size_t)N_ROWS * D_DIM / 4;   // 2097152
    const size_t NB4 = (size_t)K_CENT * D_DIM / 4;   // 262144
    size_t i = (size_t)blockIdx.x * 256 + threadIdx.x;
    if (i >= NA4 + NB4) return;
    const bool isA = (i < NA4);
    const float4 x = isA ? ((const float4*)A)[i] : ((const float4*)B)[i - NA4];
    __nv_bfloat162 lo = __floats2bfloat162_rn(x.x, x.y);
    __nv_bfloat162 hi = __floats2bfloat162_rn(x.z, x.w);
    size_t e = (isA ? i : (i - NA4));
    __nv_bfloat162* d = (__nv_bfloat162*)(isA ? g_Abf : g_Bbf);
    d[e * 2]     = lo;
    d[e * 2 + 1] = hi;
}

// ---------------- kernel: reset count histogram ------------------------------
__global__ void vq_init() {
    int t = threadIdx.x;
    for (int k = t; k < K_CENT; k += 256) g_counts[k] = 0;
}

// ---------------- kernel: mma.sync bf16 GEMM  sim = A @ B^T ------------------
#define GBM 128
#define GBN 128
#define GSTAGE_BYTES 20480        // A tile 10240 + B tile 10240 (128 rows x 40 halves)
#define GSM_TOTAL (3 * GSTAGE_BYTES)   // 61440
#define NKSTEP 16                 // 512 / 32

__device__ __forceinline__ void g_load_stage(uint32_t smemU, int st, int kstep,
                                             int m0, int n0, int tid) {
    const int kin = kstep * 32;
    const __nv_bfloat16* __restrict__ gA = g_Abf;
    const __nv_bfloat16* __restrict__ gB = g_Bbf;
    const uint32_t sA = smemU + st * GSTAGE_BYTES;
    const uint32_t sB = sA + 10240;
#pragma unroll
    for (int h = 0; h < 2; h++) {
        const int c = tid + h * 256;            // 0..511
        const int row = c >> 2, q = c & 3;
        const void* srcA = gA + (size_t)(m0 + row) * D_DIM + kin + q * 8;
        const uint32_t dstA = sA + row * 80 + q * 16;
        asm volatile("cp.async.cg.shared.global [%0], [%1], 16;" :: "r"(dstA), "l"(srcA));
        const void* srcB = gB + (size_t)(n0 + row) * D_DIM + kin + q * 8;
        const uint32_t dstB = sB + row * 80 + q * 16;
        asm volatile("cp.async.cg.shared.global [%0], [%1], 16;" :: "r"(dstB), "l"(srcB));
    }
}

__global__ __launch_bounds__(256, 2)
void vq_gemm_mma() {
    extern __shared__ char gsm[];
    const uint32_t smemU = smem_u32(gsm);
    const int tid = threadIdx.x;
    const int lane = tid & 31;
    const int w = tid >> 5;
    const int wm = (w & 1) * 64;       // warp m-offset in tile
    const int wn = (w >> 1) * 32;      // warp n-offset in tile
    const int n0 = blockIdx.x * GBN;
    const int m0 = blockIdx.y * GBM;

    float acc[4][4][4];
#pragma unroll
    for (int a = 0; a < 4; a++)
#pragma unroll
        for (int b = 0; b < 4; b++)
#pragma unroll
            for (int c = 0; c < 4; c++) acc[a][b][c] = 0.f;

    g_load_stage(smemU, 0, 0, m0, n0, tid);
    asm volatile("cp.async.commit_group;" ::: "memory");
    g_load_stage(smemU, 1, 1, m0, n0, tid);
    asm volatile("cp.async.commit_group;" ::: "memory");

    int st = 0, ls = 2;
    for (int i = 0; i < NKSTEP; i++) {
        if (i + 2 < NKSTEP) asm volatile("cp.async.wait_group 1;" ::: "memory");
        else                asm volatile("cp.async.wait_group 0;" ::: "memory");
        __syncthreads();
        if (i + 2 < NKSTEP) {
            g_load_stage(smemU, ls, i + 2, m0, n0, tid);
            asm volatile("cp.async.commit_group;" ::: "memory");
            ls = (ls == 2) ? 0 : ls + 1;
        }
        const uint32_t sA = smemU + st * GSTAGE_BYTES;
        const uint32_t sB = sA + 10240;
#pragma unroll
        for (int k16 = 0; k16 < 32; k16 += 16) {
            uint32_t a[4][4], b[2][4];
#pragma unroll
            for (int mt = 0; mt < 4; mt++) {
                const uint32_t addr = sA + (wm + mt * 16 + (lane & 15)) * 80
                                         + (k16 + ((lane >> 4) << 3)) * 2;
                asm volatile("ldmatrix.sync.aligned.m8n8.x4.shared.b16 {%0,%1,%2,%3}, [%4];"
                    : "=r"(a[mt][0]), "=r"(a[mt][1]), "=r"(a[mt][2]), "=r"(a[mt][3])
                    : "r"(addr));
            }
#pragma unroll
            for (int nt2 = 0; nt2 < 2; nt2++) {
                const uint32_t addr = sB + (wn + nt2 * 16 + ((lane >> 4) & 1) * 8 + (lane & 7)) * 80
                                         + (k16 + ((lane >> 3) & 1) * 8) * 2;
                asm volatile("ldmatrix.sync.aligned.m8n8.x4.shared.b16 {%0,%1,%2,%3}, [%4];"
                    : "=r"(b[nt2][0]), "=r"(b[nt2][1]), "=r"(b[nt2][2]), "=r"(b[nt2][3])
                    : "r"(addr));
            }
#pragma unroll
            for (int mt = 0; mt < 4; mt++)
#pragma unroll
                for (int nt = 0; nt < 4; nt++) {
                    asm volatile(
                        "mma.sync.aligned.m16n8k16.row.col.f32.bf16.bf16.f32 "
                        "{%0,%1,%2,%3},{%4,%5,%6,%7},{%8,%9},{%0,%1,%2,%3};"
                        : "+f"(acc[mt][nt][0]), "+f"(acc[mt][nt][1]),
                          "+f"(acc[mt][nt][2]), "+f"(acc[mt][nt][3])
                        : "r"(a[mt][0]), "r"(a[mt][1]), "r"(a[mt][2]), "r"(a[mt][3]),
                          "r"(b[nt >> 1][(nt & 1) * 2]), "r"(b[nt >> 1][(nt & 1) * 2 + 1]));
                }
        }
        st = (st == 2) ? 0 : st + 1;
    }

    // epilogue: bf16 stores
#pragma unroll
    for (int mt = 0; mt < 4; mt++) {
        const int r0 = m0 + wm + mt * 16 + (lane >> 2);
        const int cb = n0 + wn + (lane & 3) * 2;
#pragma unroll
        for (int nt = 0; nt < 4; nt++) {
            __nv_bfloat16* p0 = g_simh + (size_t)r0 * K_CENT + cb + nt * 8;
            __nv_bfloat16* p1 = p0 + (size_t)8 * K_CENT;
            *(__nv_bfloat162*)p0 = __floats2bfloat162_rn(acc[mt][nt][0], acc[mt][nt][1]);
            *(__nv_bfloat162*)p1 = __floats2bfloat162_rn(acc[mt][nt][2], acc[mt][nt][3]);
        }
    }
}

// ---------------- kernel: softmax / exact argmax / entropy / diversity -------
// thread t owns columns [8t, 8t+8) of every row; diversity partials in registers
__global__ __launch_bounds__(256)
void vq_softmax(const float* __restrict__ inputs, const float* __restrict__ codebook,
                float* __restrict__ out_idx) {
    __shared__ float warr[8], wS[8], wT[8];
    __shared__ int   cand[32];
    __shared__ int   ncand;
    const int t = threadIdx.x;
    const int lane = t & 31;
    const int w = t >> 5;
    const int row0 = blockIdx.x * ROWS_PER_BLK;

    float pdiv[8];
#pragma unroll
    for (int j = 0; j < 8; j++) pdiv[j] = 0.f;
    float hacc = 0.f;

    for (int r = 0; r < ROWS_PER_BLK; ++r) {
        const int n = row0 + r;
        // one uint4 = 8 consecutive bf16 columns per thread
        const uint4 raw = ((const uint4*)g_simh)[(size_t)n * (K_CENT / 8) + t];
        float v[8];
        {
            const __nv_bfloat162* h2 = (const __nv_bfloat162*)&raw;
#pragma unroll
            for (int p = 0; p < 4; p++) {
                float2 f = __bfloat1622float2(h2[p]);
                v[p * 2] = f.x; v[p * 2 + 1] = f.y;
            }
        }

        float mv = v[0];
#pragma unroll
        for (int j = 1; j < 8; j++) mv = fmaxf(mv, v[j]);
#pragma unroll
        for (int o = 16; o > 0; o >>= 1) mv = fmaxf(mv, __shfl_xor_sync(0xffffffffu, mv, o));
        if (lane == 0) warr[w] = mv;
        if (t == 0) ncand = 0;
        __syncthreads();
        float rowmax = warr[0];
#pragma unroll
        for (int k = 1; k < 8; k++) rowmax = fmaxf(rowmax, warr[k]);

        // candidates within DELTA of approx max (exact refinement below)
#pragma unroll
        for (int j = 0; j < 8; j++) {
            if (v[j] >= rowmax - DELTA) {
                int s = atomicAdd(&ncand, 1);
                if (s < 32) cand[s] = t * 8 + j;
            }
        }

        float e[8], ls = 0.f, ts = 0.f;
#pragma unroll
        for (int j = 0; j < 8; j++) {
            float u = v[j] - rowmax;
            float ee = __expf(u);
            e[j] = ee; ls += ee; ts += ee * u;
        }
#pragma unroll
        for (int o = 16; o > 0; o >>= 1) {
            ls += __shfl_xor_sync(0xffffffffu, ls, o);
            ts += __shfl_xor_sync(0xffffffffu, ts, o);
        }
        if (lane == 0) { wS[w] = ls; wT[w] = ts; }
        __syncthreads();
        float S = 0.f, T = 0.f;
#pragma unroll
        for (int k = 0; k < 8; k++) { S += wS[k]; T += wT[k]; }
        const float invS = 1.0f / S;

#pragma unroll
        for (int j = 0; j < 8; j++) pdiv[j] += e[j] * invS;
        // sum_k p*log2(p) = log2e*(T/S) - log2(S)   (eps inside log is negligible)
        if (t == 0) hacc += 1.44269504f * (T * invS) - __log2f(S);

        // exact fp32 refinement of argmax (warp 0) — numerics frozen
        if (w == 0) {
            const int nc = min(ncand, 32);
            float bestv = -3.4e38f; int besti = 0x7fffffff;
            const float4* ar = (const float4*)(inputs + (size_t)n * D_DIM);
            for (int c = 0; c < nc; ++c) {
                const int k = cand[c];
                const float4* br = (const float4*)(codebook + (size_t)k * D_DIM);
                float part = 0.f;
#pragma unroll 4
                for (int i = lane; i < D_DIM / 4; i += 32) {
                    float4 a = ar[i], b = br[i];
                    part += a.x * b.x + a.y * b.y + a.z * b.z + a.w * b.w;
                }
#pragma unroll
                for (int o = 16; o > 0; o >>= 1)
                    part += __shfl_xor_sync(0xffffffffu, part, o);
                if (part > bestv || (part == bestv && k < besti)) { bestv = part; besti = k; }
            }
            if (lane == 0) {
                g_nn[n] = besti;
                out_idx[n] = (float)besti;
                atomicAdd(&g_counts[besti], 1);
            }
        }
        __syncthreads();
    }

    float* dp = g_div_part + (size_t)blockIdx.x * K_CENT + t * 8;
    *(float4*)(dp)     = make_float4(pdiv[0], pdiv[1], pdiv[2], pdiv[3]);
    *(float4*)(dp + 4) = make_float4(pdiv[4], pdiv[5], pdiv[6], pdiv[7]);
    if (t == 0) g_h_part[blockIdx.x] = hacc;
}

// ---------------- kernel: deterministic diversity reduction ------------------
__global__ __launch_bounds__(256)
void vq_div_reduce() {
    const int k = blockIdx.x * 256 + threadIdx.x;  // 0..2047 (gridDim.x = 8)
    const int chunk = blockIdx.y;                  // 0..15
    const int b0 = chunk * 64;
    float s0 = 0.f, s1 = 0.f, s2 = 0.f, s3 = 0.f;
    for (int b = 0; b < 64; b += 4) {
        s0 += g_div_part[(size_t)(b0 + b + 0) * K_CENT + k];
        s1 += g_div_part[(size_t)(b0 + b + 1) * K_CENT + k];
        s2 += g_div_part[(size_t)(b0 + b + 2) * K_CENT + k];
        s3 += g_div_part[(size_t)(b0 + b + 3) * K_CENT + k];
    }
    g_div2[chunk * K_CENT + k] = (s0 + s1) + (s2 + s3);
}

// ---------------- kernel: finalize loss + EMA counts -------------------------
__global__ __launch_bounds__(256)
void vq_finalize(const float* __restrict__ cluster_counts,
                 const int* __restrict__ train,
                 float* __restrict__ out_counts) {
    __shared__ float redf[256];
    const int t = threadIdx.x;
    const int tr = train[0];

    float hdiv = 0.f;
    for (int k = t; k < K_CENT; k += 256) {
        float s = 0.f;
#pragma unroll
        for (int ch = 0; ch < 16; ch++) s += g_div2[ch * K_CENT + k];
        float d = s * (1.0f / (float)N_ROWS);
        hdiv += d * __log2f(d + EPSF);
        float cnt = (float)g_counts[k];
        float oc  = cluster_counts[k];
        out_counts[k] = tr ? (EMA * oc + (1.0f - EMA) * cnt) : oc;
    }
    float hsum = 0.f;
    for (int i = t; i < NBLK_SM; i += 256) hsum += g_h_part[i];

    redf[t] = hdiv;
    __syncthreads();
    for (int s = 128; s > 0; s >>= 1) { if (t < s) redf[t] += redf[t + s]; __syncthreads(); }
    const float hdiv_tot = redf[0];
    __syncthreads();
    redf[t] = hsum;
    __syncthreads();
    for (int s = 128; s > 0; s >>= 1) { if (t < s) redf[t] += redf[t + s]; __syncthreads(); }
    if (t == 0) {
        float h_clust     = -(redf[0] / (float)N_ROWS);
        float h_diversity = -hdiv_tot;
        g_loss = h_clust - GAMMAF * h_diversity;
    }
}

// ---------------- kernel: broadcast-fill quantization_loss -------------------
__global__ __launch_bounds__(256)
void vq_fill(float* __restrict__ dst) {
    const float v = g_loss;
    const float4 f = make_float4(v, v, v, v);
    size_t i = (size_t)blockIdx.x * 256 + threadIdx.x;
#pragma unroll
    for (int j = 0; j < 4; j++)
        ((float4*)dst)[i + (size_t)j * 2097152] = f;
}

// ---------------- kernel: gather + center + normalize + STE ------------------
__global__ __launch_bounds__(128)
void vq_quantize(const float* __restrict__ inputs,
                 const float* __restrict__ codebook,
                 float* __restrict__ out_q) {
    __shared__ float red[128];
    const int n = blockIdx.x;
    const int t = threadIdx.x;
    const int idx = g_nn[n];

    const float4 q = ((const float4*)(codebook + (size_t)idx * D_DIM))[t];
    red[t] = q.x + q.y + q.z + q.w;
    __syncthreads();
    for (int s = 64; s > 0; s >>= 1) { if (t < s) red[t] += red[t + s]; __syncthreads(); }
    const float mean = red[0] * (1.0f / (float)D_DIM);
    __syncthreads();

    const float cx = q.x - mean, cy = q.y - mean, cz = q.z - mean, cw = q.w - mean;
    red[t] = cx * cx + cy * cy + cz * cz + cw * cw;
    __syncthreads();
    for (int s = 64; s > 0; s >>= 1) { if (t < s) red[t] += red[t + s]; __syncthreads(); }
    const float inv = 1.0f / sqrtf(red[0]);

    const float4 x = ((const float4*)(inputs + (size_t)n * D_DIM))[t];
    float4 o;
    o.x = x.x + (cx * inv - x.x);
    o.y = x.y + (cy * inv - x.y);
    o.z = x.z + (cz * inv - x.z);
    o.w = x.w + (cw * inv - x.w);
    ((float4*)out_q)[(size_t)n * (D_DIM / 4) + t] = o;
}

// ---------------- launcher ---------------------------------------------------
extern "C" void kernel_launch(void* const* d_in, const int* in_sizes, int n_in,
                              void* d_out, int out_size) {
    const float* inputs   = (const float*)d_in[0];
    const float* codebook = (const float*)d_in[1];
    const float* ccounts  = (const float*)d_in[2];
    const int*   train    = (const int*)d_in[3];
    float* out = (float*)d_out;

    static bool attr_set = false;
    if (!attr_set) {
        cudaFuncSetAttribute(vq_gemm_mma, cudaFuncAttributeMaxDynamicSharedMemorySize, GSM_TOTAL);
        attr_set = true;
    }

    vq_convert<<<9216, 256>>>(inputs, codebook);
    vq_init<<<1, 256>>>();
    vq_gemm_mma<<<dim3(K_CENT / GBN, N_ROWS / GBM), 256, GSM_TOTAL>>>();
    vq_softmax<<<NBLK_SM, 256>>>(inputs, codebook, out + OFF_IDX);
    vq_div_reduce<<<dim3(8, 16), 256>>>();
    vq_finalize<<<1, 256>>>(ccounts, train, out + OFF_CNT);
    vq_fill<<<8192, 256>>>(out + OFF_LOSS);
    vq_quantize<<<N_ROWS, 128>>>(inputs, codebook, out + OFF_Q);
    cudaMemcpyAsync(out + OFF_CB, d_in[1], (size_t)K_CENT * D_DIM * sizeof(float),
                    cudaMemcpyDeviceToDevice, 0);
    (void)in_sizes; (void)n_in; (void)out_size;
}

// round 7
// speedup vs baseline: 3.7814x; 1.0499x over previous
#include <cuda_runtime.h>
#include <cuda_bf16.h>
#include <cstdint>
#include <cstddef>

// Problem constants
#define N_ROWS   16384
#define D_DIM    512
#define K_CENT   2048
#define EMA      0.99f
#define GAMMAF   1.0f
#define EPSF     1e-8f
#define DELTA    1.5e-2f
#define ROWS_PER_BLK 16
#define NBLK_SM  (N_ROWS / ROWS_PER_BLK)   // 1024

// Output layout (float32, concatenated in reference return order)
#define OFF_Q    ((size_t)0)
#define OFF_LOSS ((size_t)8388608)
#define OFF_IDX  ((size_t)41943040)
#define OFF_CB   ((size_t)41959424)
#define OFF_CNT  ((size_t)43008000)

// ---------------- scratch (static device memory) -----------------------------
__device__ __align__(16) __nv_bfloat16 g_simh[(size_t)N_ROWS * K_CENT];   // 67 MB
__device__ float g_div_part[(size_t)NBLK_SM * K_CENT];    // 8 MB
__device__ float g_div2[16 * K_CENT];
__device__ float g_h_part[NBLK_SM];
__device__ int   g_counts[K_CENT];
__device__ float g_loss;
__device__ int   g_cand[(size_t)N_ROWS * 32];             // 2 MB
__device__ int   g_ncand[N_ROWS];
__device__ __align__(16) __nv_bfloat16 g_Abf[(size_t)N_ROWS * D_DIM];  // 16.8 MB
__device__ __align__(16) __nv_bfloat16 g_Bbf[(size_t)K_CENT * D_DIM];  // 2 MB

__device__ __forceinline__ uint32_t smem_u32(const void* p) {
    uint32_t a;
    asm("{ .reg .u64 t; cvta.to.shared.u64 t, %1; cvt.u32.u64 %0, t; }" : "=r"(a) : "l"(p));
    return a;
}

// ---------------- kernel: fp32 -> bf16 convert --------------------------------
__global__ __launch_bounds__(256)
void vq_convert(const float* __restrict__ A, const float* __restrict__ B) {
    const size_t NA4 = (size_t)N_ROWS * D_DIM / 4;   // 2097152
    const size_t NB4 = (size_t)K_CENT * D_DIM / 4;   // 262144
    size_t i = (size_t)blockIdx.x * 256 + threadIdx.x;
    if (i >= NA4 + NB4) return;
    const bool isA = (i < NA4);
    const float4 x = isA ? ((const float4*)A)[i] : ((const float4*)B)[i - NA4];
    __nv_bfloat162 lo = __floats2bfloat162_rn(x.x, x.y);
    __nv_bfloat162 hi = __floats2bfloat162_rn(x.z, x.w);
    size_t e = (isA ? i : (i - NA4));
    __nv_bfloat162* d = (__nv_bfloat162*)(isA ? g_Abf : g_Bbf);
    d[e * 2]     = lo;
    d[e * 2 + 1] = hi;
}

// ---------------- kernel: reset counters --------------------------------------
__global__ __launch_bounds__(256)
void vq_init() {
    int i = blockIdx.x * 256 + threadIdx.x;
    if (i < N_ROWS) g_ncand[i] = 0;
    if (i < K_CENT) g_counts[i] = 0;
}

// ---------------- kernel: mma.sync bf16 GEMM  sim = A @ B^T ------------------
// tile 128(M) x 256(N), BK=32, 3-stage cp.async pipeline
#define GBM 128
#define GBN 256
#define GSTAGE_BYTES 30720        // A 128x80B=10240 + B 256x80B=20480
#define GSM_TOTAL (3 * GSTAGE_BYTES)   // 92160
#define NKSTEP 16                 // 512 / 32

__device__ __forceinline__ void g_load_stage(uint32_t smemU, int st, int kstep,
                                             int m0, int n0, int tid) {
    const int kin = kstep * 32;
    const uint32_t sA = smemU + st * GSTAGE_BYTES;
    const uint32_t sB = sA + 10240;
#pragma unroll
    for (int h = 0; h < 6; h++) {
        const int c = tid + h * 256;            // 0..1535
        if (c < 512) {
            const int row = c >> 2, q = c & 3;
            const void* src = g_Abf + (size_t)(m0 + row) * D_DIM + kin + q * 8;
            const uint32_t dst = sA + row * 80 + q * 16;
            asm volatile("cp.async.cg.shared.global [%0], [%1], 16;" :: "r"(dst), "l"(src));
        } else {
            const int c2 = c - 512;
            const int row = c2 >> 2, q = c2 & 3;
            const void* src = g_Bbf + (size_t)(n0 + row) * D_DIM + kin + q * 8;
            const uint32_t dst = sB + row * 80 + q * 16;
            asm volatile("cp.async.cg.shared.global [%0], [%1], 16;" :: "r"(dst), "l"(src));
        }
    }
}

__global__ __launch_bounds__(256, 1)
void vq_gemm_mma() {
    extern __shared__ char gsm[];
    const uint32_t smemU = smem_u32(gsm);
    const int tid = threadIdx.x;
    const int lane = tid & 31;
    const int w = tid >> 5;
    const int wm = (w & 1) * 64;       // warp m-offset (2 warps in M)
    const int wn = (w >> 1) * 64;      // warp n-offset (4 warps in N)
    const int n0 = blockIdx.x * GBN;
    const int m0 = blockIdx.y * GBM;

    float acc[4][8][4];
#pragma unroll
    for (int a = 0; a < 4; a++)
#pragma unroll
        for (int b = 0; b < 8; b++)
#pragma unroll
            for (int c = 0; c < 4; c++) acc[a][b][c] = 0.f;

    g_load_stage(smemU, 0, 0, m0, n0, tid);
    asm volatile("cp.async.commit_group;" ::: "memory");
    g_load_stage(smemU, 1, 1, m0, n0, tid);
    asm volatile("cp.async.commit_group;" ::: "memory");

    int st = 0, ls = 2;
    for (int i = 0; i < NKSTEP; i++) {
        if (i + 2 < NKSTEP) asm volatile("cp.async.wait_group 1;" ::: "memory");
        else                asm volatile("cp.async.wait_group 0;" ::: "memory");
        __syncthreads();
        if (i + 2 < NKSTEP) {
            g_load_stage(smemU, ls, i + 2, m0, n0, tid);
            asm volatile("cp.async.commit_group;" ::: "memory");
            ls = (ls == 2) ? 0 : ls + 1;
        }
        const uint32_t sA = smemU + st * GSTAGE_BYTES;
        const uint32_t sB = sA + 10240;
#pragma unroll
        for (int k16 = 0; k16 < 32; k16 += 16) {
            uint32_t a[4][4], b[4][4];
#pragma unroll
            for (int mt = 0; mt < 4; mt++) {
                const uint32_t addr = sA + (wm + mt * 16 + (lane & 15)) * 80
                                         + (k16 + ((lane >> 4) << 3)) * 2;
                asm volatile("ldmatrix.sync.aligned.m8n8.x4.shared.b16 {%0,%1,%2,%3}, [%4];"
                    : "=r"(a[mt][0]), "=r"(a[mt][1]), "=r"(a[mt][2]), "=r"(a[mt][3])
                    : "r"(addr));
            }
#pragma unroll
            for (int nt2 = 0; nt2 < 4; nt2++) {
                const uint32_t addr = sB + (wn + nt2 * 16 + ((lane >> 4) & 1) * 8 + (lane & 7)) * 80
                                         + (k16 + ((lane >> 3) & 1) * 8) * 2;
                asm volatile("ldmatrix.sync.aligned.m8n8.x4.shared.b16 {%0,%1,%2,%3}, [%4];"
                    : "=r"(b[nt2][0]), "=r"(b[nt2][1]), "=r"(b[nt2][2]), "=r"(b[nt2][3])
                    : "r"(addr));
            }
#pragma unroll
            for (int mt = 0; mt < 4; mt++)
#pragma unroll
                for (int nt = 0; nt < 8; nt++) {
                    asm volatile(
                        "mma.sync.aligned.m16n8k16.row.col.f32.bf16.bf16.f32 "
                        "{%0,%1,%2,%3},{%4,%5,%6,%7},{%8,%9},{%0,%1,%2,%3};"
                        : "+f"(acc[mt][nt][0]), "+f"(acc[mt][nt][1]),
                          "+f"(acc[mt][nt][2]), "+f"(acc[mt][nt][3])
                        : "r"(a[mt][0]), "r"(a[mt][1]), "r"(a[mt][2]), "r"(a[mt][3]),
                          "r"(b[nt >> 1][(nt & 1) * 2]), "r"(b[nt >> 1][(nt & 1) * 2 + 1]));
                }
        }
        st = (st == 2) ? 0 : st + 1;
    }

    // epilogue: bf16 stores
#pragma unroll
    for (int mt = 0; mt < 4; mt++) {
        const int r0 = m0 + wm + mt * 16 + (lane >> 2);
        const int cb = n0 + wn + (lane & 3) * 2;
#pragma unroll
        for (int nt = 0; nt < 8; nt++) {
            __nv_bfloat16* p0 = g_simh + (size_t)r0 * K_CENT + cb + nt * 8;
            __nv_bfloat16* p1 = p0 + (size_t)8 * K_CENT;
            *(__nv_bfloat162*)p0 = __floats2bfloat162_rn(acc[mt][nt][0], acc[mt][nt][1]);
            *(__nv_bfloat162*)p1 = __floats2bfloat162_rn(acc[mt][nt][2], acc[mt][nt][3]);
        }
    }
}

// ---------------- kernel: softmax / candidates / entropy / diversity ---------
// thread t owns columns [8t, 8t+8) of every row; diversity partials in registers
__global__ __launch_bounds__(256)
void vq_softmax() {
    __shared__ float warr[8], wS[8], wT[8];
    const int t = threadIdx.x;
    const int lane = t & 31;
    const int w = t >> 5;
    const int row0 = blockIdx.x * ROWS_PER_BLK;

    float pdiv[8];
#pragma unroll
    for (int j = 0; j < 8; j++) pdiv[j] = 0.f;
    float hacc = 0.f;

    for (int r = 0; r < ROWS_PER_BLK; ++r) {
        const int n = row0 + r;
        const uint4 raw = ((const uint4*)g_simh)[(size_t)n * (K_CENT / 8) + t];
        float v[8];
        {
            const __nv_bfloat162* h2 = (const __nv_bfloat162*)&raw;
#pragma unroll
            for (int p = 0; p < 4; p++) {
                float2 f = __bfloat1622float2(h2[p]);
                v[p * 2] = f.x; v[p * 2 + 1] = f.y;
            }
        }

        float mv = v[0];
#pragma unroll
        for (int j = 1; j < 8; j++) mv = fmaxf(mv, v[j]);
#pragma unroll
        for (int o = 16; o > 0; o >>= 1) mv = fmaxf(mv, __shfl_xor_sync(0xffffffffu, mv, o));
        if (lane == 0) warr[w] = mv;
        __syncthreads();
        float rowmax = warr[0];
#pragma unroll
        for (int k = 1; k < 8; k++) rowmax = fmaxf(rowmax, warr[k]);

        // candidates within DELTA of approx max -> global list (order-independent winner)
#pragma unroll
        for (int j = 0; j < 8; j++) {
            if (v[j] >= rowmax - DELTA) {
                int s = atomicAdd(&g_ncand[n], 1);
                if (s < 32) g_cand[(size_t)n * 32 + s] = t * 8 + j;
            }
        }

        float e[8], ls = 0.f, ts = 0.f;
#pragma unroll
        for (int j = 0; j < 8; j++) {
            float u = v[j] - rowmax;
            float ee = __expf(u);
            e[j] = ee; ls += ee; ts += ee * u;
        }
#pragma unroll
        for (int o = 16; o > 0; o >>= 1) {
            ls += __shfl_xor_sync(0xffffffffu, ls, o);
            ts += __shfl_xor_sync(0xffffffffu, ts, o);
        }
        if (lane == 0) { wS[w] = ls; wT[w] = ts; }
        __syncthreads();
        float S = 0.f, T = 0.f;
#pragma unroll
        for (int k = 0; k < 8; k++) { S += wS[k]; T += wT[k]; }
        const float invS = 1.0f / S;

#pragma unroll
        for (int j = 0; j < 8; j++) pdiv[j] += e[j] * invS;
        // sum_k p*log2(p) = log2e*(T/S) - log2(S)
        if (t == 0) hacc += 1.44269504f * (T * invS) - __log2f(S);
    }

    float* dp = g_div_part + (size_t)blockIdx.x * K_CENT + t * 8;
    *(float4*)(dp)     = make_float4(pdiv[0], pdiv[1], pdiv[2], pdiv[3]);
    *(float4*)(dp + 4) = make_float4(pdiv[4], pdiv[5], pdiv[6], pdiv[7]);
    if (t == 0) g_h_part[blockIdx.x] = hacc;
}

// ---------------- kernel: exact argmax refine + counts + quantize (fused) ----
// one warp per row
__global__ __launch_bounds__(256)
void vq_refine(const float* __restrict__ inputs, const float* __restrict__ codebook,
               float* __restrict__ out_idx, float* __restrict__ out_q) {
    const int t = threadIdx.x;
    const int lane = t & 31;
    const int w = t >> 5;
    const int n = blockIdx.x * 8 + w;

    const int nc = min(g_ncand[n], 32);
    float bestv = -3.4e38f; int besti = 0x7fffffff;
    const float4* ar = (const float4*)(inputs + (size_t)n * D_DIM);
    for (int c = 0; c < nc; ++c) {
        const int k = g_cand[(size_t)n * 32 + c];
        const float4* br = (const float4*)(codebook + (size_t)k * D_DIM);
        float part = 0.f;
#pragma unroll 4
        for (int i = lane; i < D_DIM / 4; i += 32) {
            float4 a = ar[i], b = br[i];
            part += a.x * b.x + a.y * b.y + a.z * b.z + a.w * b.w;
        }
#pragma unroll
        for (int o = 16; o > 0; o >>= 1)
            part += __shfl_xor_sync(0xffffffffu, part, o);
        if (part > bestv || (part == bestv && k < besti)) { bestv = part; besti = k; }
    }
    if (lane == 0) {
        out_idx[n] = (float)besti;
        atomicAdd(&g_counts[besti], 1);
    }

    // fused quantize: center, normalize, STE
    const float4* br = (const float4*)(codebook + (size_t)besti * D_DIM);
    float4 q[4];
    float s = 0.f;
#pragma unroll
    for (int i = 0; i < 4; i++) {
        q[i] = br[lane + 32 * i];
        s += q[i].x + q[i].y + q[i].z + q[i].w;
    }
#pragma unroll
    for (int o = 16; o > 0; o >>= 1) s += __shfl_xor_sync(0xffffffffu, s, o);
    const float mean = s * (1.0f / (float)D_DIM);

    float ss = 0.f;
#pragma unroll
    for (int i = 0; i < 4; i++) {
        q[i].x -= mean; q[i].y -= mean; q[i].z -= mean; q[i].w -= mean;
        ss += q[i].x * q[i].x + q[i].y * q[i].y + q[i].z * q[i].z + q[i].w * q[i].w;
    }
#pragma unroll
    for (int o = 16; o > 0; o >>= 1) ss += __shfl_xor_sync(0xffffffffu, ss, o);
    const float inv = 1.0f / sqrtf(ss);

    float4* oq = (float4*)(out_q + (size_t)n * D_DIM);
#pragma unroll
    for (int i = 0; i < 4; i++) {
        const float4 x = ar[lane + 32 * i];
        float4 o;
        o.x = x.x + (q[i].x * inv - x.x);
        o.y = x.y + (q[i].y * inv - x.y);
        o.z = x.z + (q[i].z * inv - x.z);
        o.w = x.w + (q[i].w * inv - x.w);
        oq[lane + 32 * i] = o;
    }
}

// ---------------- kernel: deterministic diversity reduction ------------------
__global__ __launch_bounds__(256)
void vq_div_reduce() {
    const int k = blockIdx.x * 256 + threadIdx.x;  // 0..2047 (gridDim.x = 8)
    const int chunk = blockIdx.y;                  // 0..15
    const int b0 = chunk * 64;
    float s0 = 0.f, s1 = 0.f, s2 = 0.f, s3 = 0.f;
    for (int b = 0; b < 64; b += 4) {
        s0 += g_div_part[(size_t)(b0 + b + 0) * K_CENT + k];
        s1 += g_div_part[(size_t)(b0 + b + 1) * K_CENT + k];
        s2 += g_div_part[(size_t)(b0 + b + 2) * K_CENT + k];
        s3 += g_div_part[(size_t)(b0 + b + 3) * K_CENT + k];
    }
    g_div2[chunk * K_CENT + k] = (s0 + s1) + (s2 + s3);
}

// ---------------- kernel: finalize loss + EMA counts -------------------------
__global__ __launch_bounds__(256)
void vq_finalize(const float* __restrict__ cluster_counts,
                 const int* __restrict__ train,
                 float* __restrict__ out_counts) {
    __shared__ float redf[256];
    const int t = threadIdx.x;
    const int tr = train[0];

    float hdiv = 0.f;
    for (int k = t; k < K_CENT; k += 256) {
        float s = 0.f;
#pragma unroll
        for (int ch = 0; ch < 16; ch++) s += g_div2[ch * K_CENT + k];
        float d = s * (1.0f / (float)N_ROWS);
        hdiv += d * __log2f(d + EPSF);
        float cnt = (float)g_counts[k];
        float oc  = cluster_counts[k];
        out_counts[k] = tr ? (EMA * oc + (1.0f - EMA) * cnt) : oc;
    }
    float hsum = 0.f;
    for (int i = t; i < NBLK_SM; i += 256) hsum += g_h_part[i];

    redf[t] = hdiv;
    __syncthreads();
    for (int s = 128; s > 0; s >>= 1) { if (t < s) redf[t] += redf[t + s]; __syncthreads(); }
    const float hdiv_tot = redf[0];
    __syncthreads();
    redf[t] = hsum;
    __syncthreads();
    for (int s = 128; s > 0; s >>= 1) { if (t < s) redf[t] += redf[t + s]; __syncthreads(); }
    if (t == 0) {
        float h_clust     = -(redf[0] / (float)N_ROWS);
        float h_diversity = -hdiv_tot;
        g_loss = h_clust - GAMMAF * h_diversity;
    }
}

// ---------------- kernel: broadcast-fill quantization_loss -------------------
__global__ __launch_bounds__(256)
void vq_fill(float* __restrict__ dst) {
    const float v = g_loss;
    const float4 f = make_float4(v, v, v, v);
    size_t i = (size_t)blockIdx.x * 256 + threadIdx.x;
#pragma unroll
    for (int j = 0; j < 4; j++)
        ((float4*)dst)[i + (size_t)j * 2097152] = f;
}

// ---------------- launcher ---------------------------------------------------
extern "C" void kernel_launch(void* const* d_in, const int* in_sizes, int n_in,
                              void* d_out, int out_size) {
    const float* inputs   = (const float*)d_in[0];
    const float* codebook = (const float*)d_in[1];
    const float* ccounts  = (const float*)d_in[2];
    const int*   train    = (const int*)d_in[3];
    float* out = (float*)d_out;

    static bool attr_set = false;
    if (!attr_set) {
        cudaFuncSetAttribute(vq_gemm_mma, cudaFuncAttributeMaxDynamicSharedMemorySize, GSM_TOTAL);
        attr_set = true;
    }

    vq_convert<<<9216, 256>>>(inputs, codebook);
    vq_init<<<64, 256>>>();
    vq_gemm_mma<<<dim3(K_CENT / GBN, N_ROWS / GBM), 256, GSM_TOTAL>>>();
    vq_softmax<<<NBLK_SM, 256>>>();
    vq_refine<<<N_ROWS / 8, 256>>>(inputs, codebook, out + OFF_IDX, out + OFF_Q);
    vq_div_reduce<<<dim3(8, 16), 256>>>();
    vq_finalize<<<1, 256>>>(ccounts, train, out + OFF_CNT);
    vq_fill<<<8192, 256>>>(out + OFF_LOSS);
    cudaMemcpyAsync(out + OFF_CB, d_in[1], (size_t)K_CENT * D_DIM * sizeof(float),
                    cudaMemcpyDeviceToDevice, 0);
    (void)in_sizes; (void)n_in; (void)out_size;
}